// round 10
// baseline (speedup 1.0000x reference)
#include <cuda_runtime.h>
#include <math.h>

#define BB   16
#define NN   16000
#define GG   128
#define NPG  (NN + GG)          /* 16128 = 63 * 256 exactly */
#define IMGW 800.0f
#define IMGH 800.0f
#define XCLIP 4.135166556742356f   /* log(1000/16) */
#define MAXWH 64.0f             /* boxes are at most 64px wide/tall */

#define NBX   25                /* 25x25 bins of 32px */
#define NBINS (NBX * NBX)       /* 625 */
#define BINW_INV (25.0f / 800.0f)

#define GRID_X (NPG / 256)      /* 63 */

// Per-GT argmax keys: (q_bits<<32) | (0xFFFFFFFF - idx).
// Zero at module load == "no hit"; decode_kernel consumes AND re-zeroes each
// call so every graph replay starts clean.
__device__ unsigned long long g_keys[BB * GG];

__device__ __forceinline__ float4 ld4(const float* p) {
    return *reinterpret_cast<const float4*>(p);
}

// ---------------------------------------------------------------------------
// Kernel 1: IoU only — labels + per-GT argmax (exact IoU via atomicMax).
// 32px corner-bin masks (fewer candidates) + single 128-bit funnel loop
// (one warp-max instead of four) + inline GT area (no second LDS).
// ---------------------------------------------------------------------------
__global__ void __launch_bounds__(256)
iou_kernel(const float* __restrict__ props,
           const float* __restrict__ gts,
           float* __restrict__ out_labels) {
    __shared__ float4 sg[GG];
    __shared__ uint4  smask[NBINS];

    const int b   = blockIdx.y;
    const int tid = threadIdx.x;
    const float* gt_b = gts + (size_t)b * GG * 4;

    for (int i = tid; i < NBINS; i += 256)
        smask[i] = make_uint4(0u, 0u, 0u, 0u);
    __syncthreads();

    // ---- prologue: GT boxes -> smem + corner-bin masks (dilated 64px) ----
    if (tid < GG) {
        float4 v = ld4(gt_b + tid * 4);
        sg[tid] = v;
        int bx0 = (int)(fmaxf(v.x - MAXWH, 0.0f) * BINW_INV);
        int bx1 = (int)(v.z * BINW_INV); if (bx1 > NBX - 1) bx1 = NBX - 1;
        int by0 = (int)(fmaxf(v.y - MAXWH, 0.0f) * BINW_INV);
        int by1 = (int)(v.w * BINW_INV); if (by1 > NBX - 1) by1 = NBX - 1;
        const unsigned bit  = 1u << (tid & 31);
        const int      word = tid >> 5;
        unsigned int* base = reinterpret_cast<unsigned int*>(smask);
        for (int by = by0; by <= by1; by++)
            for (int bx = bx0; bx <= bx1; bx++)
                atomicOr(base + (by * NBX + bx) * 4 + word, bit);
    }
    __syncthreads();

    const int p = blockIdx.x * 256 + tid;   // grid sized exactly, p < NPG

    float label;
    if (p >= NN) {
        label = 1.0f;   // appended GT: self-IoU == 1.0, not in argmax domain
    } else {
        float4 a = ld4(props + ((size_t)b * NN + p) * 4);
        const float area_a = __fmul_rn(__fsub_rn(a.z, a.x), __fsub_rn(a.w, a.y));
        float vmax = 0.0f;
        unsigned long long* keyrow = g_keys + b * GG;
        const unsigned low = 0xFFFFFFFFu - (unsigned)p;

        const int bin = (int)(a.y * BINW_INV) * NBX + (int)(a.x * BINW_INV);
        uint4 m4 = smask[bin];
        unsigned m0 = m4.x, m1 = m4.y, m2 = m4.z, m3 = m4.w;

        // single funnel loop over the 128-bit candidate mask
        for (;;) {
            int g;
            if      (m0) { g =      __ffs(m0) - 1; m0 &= m0 - 1; }
            else if (m1) { g = 31 + __ffs(m1);     m1 &= m1 - 1; }
            else if (m2) { g = 63 + __ffs(m2);     m2 &= m2 - 1; }
            else if (m3) { g = 95 + __ffs(m3);     m3 &= m3 - 1; }
            else break;

            float4 gb = sg[g];
            float ltx = fmaxf(a.x, gb.x);
            float lty = fmaxf(a.y, gb.y);
            float rbx = fminf(a.z, gb.z);
            float rby = fminf(a.w, gb.w);
            float ww = __fsub_rn(rbx, ltx);
            float hh = __fsub_rn(rby, lty);
            if (ww > 0.0f && hh > 0.0f) {
                float area_b = __fmul_rn(__fsub_rn(gb.z, gb.x),
                                         __fsub_rn(gb.w, gb.y));
                float inter = __fmul_rn(ww, hh);
                float uni   = __fsub_rn(__fadd_rn(area_b, area_a), inter);
                float q     = __fdiv_rn(inter, uni);
                vmax = fmaxf(vmax, q);
                unsigned long long key =
                    ((unsigned long long)__float_as_uint(q) << 32) | low;
                atomicMax(keyrow + g, key);
            }
        }
        label = (vmax >= 0.5f) ? 1.0f : 0.0f;
    }
    out_labels[(size_t)b * NPG + p] = label;
}

// ---------------------------------------------------------------------------
// Kernel 2: decode+clip for all B*(N+G) boxes; its first 8 blocks (y==0)
// also run the 2048-item encode epilogue (keys -> reg_targets + roi_scores,
// then key reset). No third launch.
// ---------------------------------------------------------------------------
__global__ void __launch_bounds__(256)
decode_kernel(const float* __restrict__ props,
              const float* __restrict__ gts,
              const float* __restrict__ reg,
              float* __restrict__ out_pred,
              float* __restrict__ out_regt,
              float* __restrict__ out_scores) {
    const int b   = blockIdx.y;
    const int tid = threadIdx.x;
    const int p   = blockIdx.x * 256 + tid;

    // ---- decode + clip (outputs only: fast math) ----
    {
        float4 a = (p < NN) ? ld4(props + ((size_t)b * NN + p) * 4)
                            : ld4(gts + ((size_t)b * GG + (p - NN)) * 4);
        float4 r = ld4(reg + ((size_t)b * NPG + p) * 4);
        float pw  = a.z - a.x;
        float ph  = a.w - a.y;
        float pcx = fmaf(0.5f, pw, a.x);
        float pcy = fmaf(0.5f, ph, a.y);
        float dx = r.x * 0.1f;
        float dy = r.y * 0.1f;
        float dw = fminf(r.z * 0.2f, XCLIP);
        float dh = fminf(r.w * 0.2f, XCLIP);
        float ncx = fmaf(dx, pw, pcx);
        float ncy = fmaf(dy, ph, pcy);
        float hnw = 0.5f * __expf(dw) * pw;
        float hnh = 0.5f * __expf(dh) * ph;
        float4 o;
        o.x = fminf(fmaxf(ncx - hnw, 0.0f), IMGW);
        o.y = fminf(fmaxf(ncy - hnh, 0.0f), IMGH);
        o.z = fminf(fmaxf(ncx + hnw, 0.0f), IMGW);
        o.w = fminf(fmaxf(ncy + hnh, 0.0f), IMGH);
        *reinterpret_cast<float4*>(out_pred + ((size_t)b * NPG + p) * 4) = o;
    }

    // ---- encode epilogue, folded into the first 8 blocks ----
    if (blockIdx.y == 0 && blockIdx.x < 8) {
        int i  = blockIdx.x * 256 + tid;     // i < 2048 = BB*GG
        int bb = i >> 7;
        int g  = i & (GG - 1);

        unsigned long long key = __ldcg(&g_keys[i]);
        __stcg(&g_keys[i], 0ull);            // reset for next graph replay
        float q = __uint_as_float((unsigned)(key >> 32));
        unsigned idx = (key == 0ull) ? 0u
                     : (0xFFFFFFFFu - (unsigned)(key & 0xFFFFFFFFull));

        float4 mp = ld4(props + ((size_t)bb * NN + idx) * 4);
        float4 gb = ld4(gts + ((size_t)bb * GG + g) * 4);

        float pw  = mp.z - mp.x;
        float ph  = mp.w - mp.y;
        float pcx = fmaf(0.5f, pw, mp.x);
        float pcy = fmaf(0.5f, ph, mp.y);
        float gw  = gb.z - gb.x;
        float gh  = gb.w - gb.y;
        float gcx = fmaf(0.5f, gw, gb.x);
        float gcy = fmaf(0.5f, gh, gb.y);

        float dx = __fdividef(10.0f * (gcx - pcx), pw);
        float dy = __fdividef(10.0f * (gcy - pcy), ph);
        float dw = 5.0f * __logf(__fdividef(gw, pw));
        float dh = 5.0f * __logf(__fdividef(gh, ph));

        float* o = out_regt + (size_t)i * 4;
        o[0] = dx; o[1] = dy; o[2] = dw; o[3] = dh;
        out_scores[i] = q;
    }
}

// ---------------------------------------------------------------------------
extern "C" void kernel_launch(void* const* d_in, const int* in_sizes, int n_in,
                              void* d_out, int out_size) {
    const float* props = (const float*)d_in[0];   // (B, N, 4)
    const float* gts   = (const float*)d_in[1];   // (B, G, 4)
    const float* reg   = (const float*)d_in[2];   // (B, N+G, 4)

    float* out        = (float*)d_out;
    float* out_pred   = out;                                  // B*(N+G)*4
    float* out_regt   = out_pred + (size_t)BB * NPG * 4;      // B*G*4
    float* out_scores = out_regt + (size_t)BB * GG * 4;       // B*G
    float* out_labels = out_scores + (size_t)BB * GG;         // B*(N+G)

    dim3 gm(GRID_X, BB);
    iou_kernel<<<gm, 256>>>(props, gts, out_labels);

    decode_kernel<<<gm, 256>>>(props, gts, reg,
                               out_pred, out_regt, out_scores);
}

// round 11
// speedup vs baseline: 1.0107x; 1.0107x over previous
#include <cuda_runtime.h>
#include <math.h>

#define BB   16
#define NN   16000
#define GG   128
#define NPG  (NN + GG)          /* 16128 = 63 * 256 exactly */
#define IMGW 800.0f
#define IMGH 800.0f
#define XCLIP 4.135166556742356f   /* log(1000/16) */
#define MAXWH 64.0f             /* boxes are at most 64px wide/tall */

#define NBX   12                /* 12x12 bins (R9 config beat 25x25) */
#define NBINS (NBX * NBX)
#define BINW_INV (12.0f / 800.0f)

#define GRID_X (NPG / 256)      /* 63 */

/* decode kernel: 2 items per thread */
#define DIPB   512
#define DGRIDX 32               /* 32*512 = 16384 >= 16128 */

// Per-GT argmax keys: (q_bits<<32) | (0xFFFFFFFF - idx).
// Zero at module load == "no hit"; decode_kernel consumes AND re-zeroes each
// call so every graph replay starts clean.
__device__ unsigned long long g_keys[BB * GG];

__device__ __forceinline__ float4 ld4(const float* p) {
    return *reinterpret_cast<const float4*>(p);
}

// ---------------------------------------------------------------------------
// Kernel 1: IoU — labels + per-GT argmax (exact IoU via atomicMax).
// Corner-bin 128-bit masks, probed as two 64-bit funnel words.
// ---------------------------------------------------------------------------
__global__ void __launch_bounds__(256)
iou_kernel(const float* __restrict__ props,
           const float* __restrict__ gts,
           float* __restrict__ out_labels) {
    __shared__ float4 sg[GG];
    __shared__ uint4  smask[NBINS];

    const int b   = blockIdx.y;
    const int tid = threadIdx.x;
    const float* gt_b = gts + (size_t)b * GG * 4;

    for (int i = tid; i < NBINS; i += 256)
        smask[i] = make_uint4(0u, 0u, 0u, 0u);
    __syncthreads();

    // ---- prologue: GT boxes -> smem + corner-bin masks (dilated 64px) ----
    if (tid < GG) {
        float4 v = ld4(gt_b + tid * 4);
        sg[tid] = v;
        int bx0 = (int)(fmaxf(v.x - MAXWH, 0.0f) * BINW_INV);
        int bx1 = (int)(v.z * BINW_INV); if (bx1 > NBX - 1) bx1 = NBX - 1;
        int by0 = (int)(fmaxf(v.y - MAXWH, 0.0f) * BINW_INV);
        int by1 = (int)(v.w * BINW_INV); if (by1 > NBX - 1) by1 = NBX - 1;
        const unsigned bit  = 1u << (tid & 31);
        const int      word = tid >> 5;
        unsigned int* base = reinterpret_cast<unsigned int*>(smask);
        for (int by = by0; by <= by1; by++)
            for (int bx = bx0; bx <= bx1; bx++)
                atomicOr(base + (by * NBX + bx) * 4 + word, bit);
    }
    __syncthreads();

    const int p = blockIdx.x * 256 + tid;   // grid sized exactly, p < NPG

    float label;
    if (p >= NN) {
        label = 1.0f;   // appended GT: self-IoU == 1.0, not in argmax domain
    } else {
        float4 a = ld4(props + ((size_t)b * NN + p) * 4);
        const float area_a = __fmul_rn(__fsub_rn(a.z, a.x), __fsub_rn(a.w, a.y));
        float vmax = 0.0f;
        unsigned long long* keyrow = g_keys + b * GG;
        const unsigned low = 0xFFFFFFFFu - (unsigned)p;

        const int bin = (int)(a.y * BINW_INV) * NBX + (int)(a.x * BINW_INV);
        uint4 m4 = smask[bin];
        // little-endian: u64 low word = .x (GTs 0-31), high = .y (32-63)
        unsigned long long m0 = ((unsigned long long)m4.y << 32) | m4.x;
        unsigned long long m1 = ((unsigned long long)m4.w << 32) | m4.z;

        // funnel loop over the 128-bit candidate mask (two u64 words)
        for (;;) {
            int g;
            if      (m0) { g =      __ffsll(m0) - 1; m0 &= m0 - 1; }
            else if (m1) { g = 63 + __ffsll(m1);     m1 &= m1 - 1; }
            else break;

            float4 gb = sg[g];
            float ltx = fmaxf(a.x, gb.x);
            float lty = fmaxf(a.y, gb.y);
            float rbx = fminf(a.z, gb.z);
            float rby = fminf(a.w, gb.w);
            float ww = __fsub_rn(rbx, ltx);
            float hh = __fsub_rn(rby, lty);
            if (ww > 0.0f && hh > 0.0f) {
                float area_b = __fmul_rn(__fsub_rn(gb.z, gb.x),
                                         __fsub_rn(gb.w, gb.y));
                float inter = __fmul_rn(ww, hh);
                float uni   = __fsub_rn(__fadd_rn(area_b, area_a), inter);
                float q     = __fdiv_rn(inter, uni);
                vmax = fmaxf(vmax, q);
                unsigned long long key =
                    ((unsigned long long)__float_as_uint(q) << 32) | low;
                atomicMax(keyrow + g, key);
            }
        }
        label = (vmax >= 0.5f) ? 1.0f : 0.0f;
    }
    out_labels[(size_t)b * NPG + p] = label;
}

// ---------------------------------------------------------------------------
// Kernel 2: decode+clip, 2 boxes per thread (doubled MLP for the streaming
// path). First 8 blocks (y==0) also run the 2048-item encode epilogue
// (keys -> reg_targets + roi_scores, then key reset).
// ---------------------------------------------------------------------------
__global__ void __launch_bounds__(256)
decode_kernel(const float* __restrict__ props,
              const float* __restrict__ gts,
              const float* __restrict__ reg,
              float* __restrict__ out_pred,
              float* __restrict__ out_regt,
              float* __restrict__ out_scores) {
    const int b   = blockIdx.y;
    const int tid = threadIdx.x;
    const int p0  = blockIdx.x * DIPB + tid;

#pragma unroll
    for (int it = 0; it < 2; it++) {
        const int p = p0 + it * 256;
        if (p < NPG) {
            float4 a = (p < NN) ? ld4(props + ((size_t)b * NN + p) * 4)
                                : ld4(gts + ((size_t)b * GG + (p - NN)) * 4);
            float4 r = ld4(reg + ((size_t)b * NPG + p) * 4);
            float pw  = a.z - a.x;
            float ph  = a.w - a.y;
            float pcx = fmaf(0.5f, pw, a.x);
            float pcy = fmaf(0.5f, ph, a.y);
            float dx = r.x * 0.1f;
            float dy = r.y * 0.1f;
            float dw = fminf(r.z * 0.2f, XCLIP);
            float dh = fminf(r.w * 0.2f, XCLIP);
            float ncx = fmaf(dx, pw, pcx);
            float ncy = fmaf(dy, ph, pcy);
            float hnw = 0.5f * __expf(dw) * pw;
            float hnh = 0.5f * __expf(dh) * ph;
            float4 o;
            o.x = fminf(fmaxf(ncx - hnw, 0.0f), IMGW);
            o.y = fminf(fmaxf(ncy - hnh, 0.0f), IMGH);
            o.z = fminf(fmaxf(ncx + hnw, 0.0f), IMGW);
            o.w = fminf(fmaxf(ncy + hnh, 0.0f), IMGH);
            *reinterpret_cast<float4*>(out_pred + ((size_t)b * NPG + p) * 4) = o;
        }
    }

    // ---- encode epilogue, folded into the first 8 blocks ----
    if (blockIdx.y == 0 && blockIdx.x < 8) {
        int i  = blockIdx.x * 256 + tid;     // i < 2048 = BB*GG
        int bb = i >> 7;
        int g  = i & (GG - 1);

        unsigned long long key = __ldcg(&g_keys[i]);
        __stcg(&g_keys[i], 0ull);            // reset for next graph replay
        float q = __uint_as_float((unsigned)(key >> 32));
        unsigned idx = (key == 0ull) ? 0u
                     : (0xFFFFFFFFu - (unsigned)(key & 0xFFFFFFFFull));

        float4 mp = ld4(props + ((size_t)bb * NN + idx) * 4);
        float4 gb = ld4(gts + ((size_t)bb * GG + g) * 4);

        float pw  = mp.z - mp.x;
        float ph  = mp.w - mp.y;
        float pcx = fmaf(0.5f, pw, mp.x);
        float pcy = fmaf(0.5f, ph, mp.y);
        float gw  = gb.z - gb.x;
        float gh  = gb.w - gb.y;
        float gcx = fmaf(0.5f, gw, gb.x);
        float gcy = fmaf(0.5f, gh, gb.y);

        float dx = __fdividef(10.0f * (gcx - pcx), pw);
        float dy = __fdividef(10.0f * (gcy - pcy), ph);
        float dw = 5.0f * __logf(__fdividef(gw, pw));
        float dh = 5.0f * __logf(__fdividef(gh, ph));

        float* o = out_regt + (size_t)i * 4;
        o[0] = dx; o[1] = dy; o[2] = dw; o[3] = dh;
        out_scores[i] = q;
    }
}

// ---------------------------------------------------------------------------
extern "C" void kernel_launch(void* const* d_in, const int* in_sizes, int n_in,
                              void* d_out, int out_size) {
    const float* props = (const float*)d_in[0];   // (B, N, 4)
    const float* gts   = (const float*)d_in[1];   // (B, G, 4)
    const float* reg   = (const float*)d_in[2];   // (B, N+G, 4)

    float* out        = (float*)d_out;
    float* out_pred   = out;                                  // B*(N+G)*4
    float* out_regt   = out_pred + (size_t)BB * NPG * 4;      // B*G*4
    float* out_scores = out_regt + (size_t)BB * GG * 4;       // B*G
    float* out_labels = out_scores + (size_t)BB * GG;         // B*(N+G)

    dim3 gi(GRID_X, BB);
    iou_kernel<<<gi, 256>>>(props, gts, out_labels);

    dim3 gd(DGRIDX, BB);
    decode_kernel<<<gd, 256>>>(props, gts, reg,
                               out_pred, out_regt, out_scores);
}